// round 13
// baseline (speedup 1.0000x reference)
#include <cuda_runtime.h>
#include <math.h>

// ---------------------------------------------------------------------------
// B=8, C=64, HW=1024, D=32.
// L = x1^T (x1 x2^T) x2 ; LFD21 = LFD12^T ; X?CD via W·X?C·W^T identity;
// chan path: 16 blocks (batch x dir); row/col maxes folded into LB epilogue;
// av kernels: threshold exp + per-kk-row liveness skip + inline sums.
// ---------------------------------------------------------------------------
__device__ float g_buf[17ll * 1024 * 1024];

__device__ __forceinline__ unsigned fenc(float f)
{
    unsigned b = __float_as_uint(f);
    return (b & 0x80000000u) ? ~b : (b | 0x80000000u);
}
__device__ __forceinline__ float fdec(unsigned u)
{
    return (u & 0x80000000u) ? __uint_as_float(u & 0x7FFFFFFFu)
                             : __uint_as_float(~u);
}

// ===========================================================================
// gemm64: C[b](MxN) = opA(A[b]) * opB(B[b]); tile 64x64, KT=16, 256 thr, 4x4.
// ===========================================================================
template <bool TA, bool TB>
__global__ void __launch_bounds__(256)
gemm64_kernel(const float* __restrict__ A, const float* __restrict__ B,
              float* __restrict__ C, int M, int N, int K, long sA, long sB, long sC)
{
    __shared__ float As[16][68];
    __shared__ float Bs[16][68];
    const int tid = threadIdx.x;
    const int m0 = blockIdx.y * 64, n0 = blockIdx.x * 64;
    const float* Ab = A + (long)blockIdx.z * sA;
    const float* Bb = B + (long)blockIdx.z * sB;
    float* Cb = C + (long)blockIdx.z * sC;
    const int rowt = (tid >> 4) * 4, colt = (tid & 15) * 4;
    float acc[4][4] = {};

    for (int k0 = 0; k0 < K; k0 += 16) {
        float4 av = {0,0,0,0}, bv = {0,0,0,0};
        if (!TA) {
            int r = tid >> 2, c = (tid & 3) * 4;
            if (m0 + r < M) av = *(const float4*)(Ab + (long)(m0 + r) * K + k0 + c);
            As[c+0][r]=av.x; As[c+1][r]=av.y; As[c+2][r]=av.z; As[c+3][r]=av.w;
        } else {
            int kr = tid >> 4, mc = (tid & 15) * 4;
            if (m0 + mc < M) av = *(const float4*)(Ab + (long)(k0 + kr) * M + m0 + mc);
            *(float4*)&As[kr][mc] = av;
        }
        if (!TB) {
            int kr = tid >> 4, nc = (tid & 15) * 4;
            if (n0 + nc < N) bv = *(const float4*)(Bb + (long)(k0 + kr) * N + n0 + nc);
            *(float4*)&Bs[kr][nc] = bv;
        } else {
            int r = tid >> 2, c = (tid & 3) * 4;
            if (n0 + r < N) bv = *(const float4*)(Bb + (long)(n0 + r) * K + k0 + c);
            Bs[c+0][r]=bv.x; Bs[c+1][r]=bv.y; Bs[c+2][r]=bv.z; Bs[c+3][r]=bv.w;
        }
        __syncthreads();
#pragma unroll
        for (int kk = 0; kk < 16; kk++) {
            float4 a = *(const float4*)&As[kk][rowt];
            float4 b = *(const float4*)&Bs[kk][colt];
            float ra[4] = {a.x,a.y,a.z,a.w}, rb[4] = {b.x,b.y,b.z,b.w};
#pragma unroll
            for (int i = 0; i < 4; i++)
#pragma unroll
                for (int j = 0; j < 4; j++) acc[i][j] += ra[i] * rb[j];
        }
        __syncthreads();
    }
    if (n0 + colt < N) {
#pragma unroll
        for (int i = 0; i < 4; i++) {
            int m = m0 + rowt + i;
            if (m < M)
                *(float4*)(Cb + (long)m * N + n0 + colt) =
                    make_float4(acc[i][0], acc[i][1], acc[i][2], acc[i][3]);
        }
    }
}

static void launch_gemm64(bool ta, bool tb,
                          const float* A, const float* B, float* C,
                          int M, int N, int K, long sA, long sB, long sC, int batch)
{
    dim3 grid((N + 63) / 64, (M + 63) / 64, batch);
    if (!ta && !tb)      gemm64_kernel<false,false><<<grid,256>>>(A,B,C,M,N,K,sA,sB,sC);
    else if (!ta && tb)  gemm64_kernel<false,true ><<<grid,256>>>(A,B,C,M,N,K,sA,sB,sC);
    else if (ta && !tb)  gemm64_kernel<true ,false><<<grid,256>>>(A,B,C,M,N,K,sA,sB,sC);
    else                 gemm64_kernel<true ,true ><<<grid,256>>>(A,B,C,M,N,K,sA,sB,sC);
}

// ===========================================================================
// lbgemm: LB = x1^T @ PP (1024x1024, K=64) + row/col maxes via encoded atomics.
// ===========================================================================
__global__ void __launch_bounds__(256)
lbgemm_k(const float* __restrict__ X1, const float* __restrict__ PP,
         float* __restrict__ LB, unsigned* __restrict__ RSME, unsigned* __restrict__ CSME)
{
    __shared__ float As[16][68];
    __shared__ float Bs[16][68];
    __shared__ unsigned srow[64], scol[64];
    const int tid = threadIdx.x;
    const int m0 = blockIdx.y * 64, n0 = blockIdx.x * 64, b = blockIdx.z;
    const float* Ab = X1 + (long)b * 65536;
    const float* Bb = PP + (long)b * 65536;
    float* Cb = LB + (long)b * 1048576;
    const int rowt = (tid >> 4) * 4, colt = (tid & 15) * 4;
    const int kr = tid >> 4, xc = (tid & 15) * 4;
    float acc[4][4] = {};

    if (tid < 64) { srow[tid] = 0u; scol[tid] = 0u; }

    for (int k0 = 0; k0 < 64; k0 += 16) {
        *(float4*)&As[kr][xc] = *(const float4*)(Ab + (long)(k0 + kr) * 1024 + m0 + xc);
        *(float4*)&Bs[kr][xc] = *(const float4*)(Bb + (long)(k0 + kr) * 1024 + n0 + xc);
        __syncthreads();
#pragma unroll
        for (int kk = 0; kk < 16; kk++) {
            float4 a = *(const float4*)&As[kk][rowt];
            float4 bq = *(const float4*)&Bs[kk][colt];
            float ra[4] = {a.x,a.y,a.z,a.w}, rb[4] = {bq.x,bq.y,bq.z,bq.w};
#pragma unroll
            for (int i = 0; i < 4; i++)
#pragma unroll
                for (int j = 0; j < 4; j++) acc[i][j] += ra[i] * rb[j];
        }
        __syncthreads();
    }

#pragma unroll
    for (int i = 0; i < 4; i++)
        *(float4*)(Cb + (long)(m0 + rowt + i) * 1024 + n0 + colt) =
            make_float4(acc[i][0], acc[i][1], acc[i][2], acc[i][3]);

#pragma unroll
    for (int i = 0; i < 4; i++) {
        float rm = fmaxf(fmaxf(acc[i][0], acc[i][1]), fmaxf(acc[i][2], acc[i][3]));
        atomicMax(&srow[rowt + i], fenc(rm));
    }
#pragma unroll
    for (int j = 0; j < 4; j++) {
        float cm = fmaxf(fmaxf(acc[0][j], acc[1][j]), fmaxf(acc[2][j], acc[3][j]));
        atomicMax(&scol[colt + j], fenc(cm));
    }
    __syncthreads();
    if (tid < 64)       atomicMax(&RSME[b * 1024 + m0 + tid], srow[tid]);
    else if (tid < 128) atomicMax(&CSME[b * 1024 + n0 + (tid - 64)], scol[tid - 64]);
}

// ===========================================================================
// trio_k: three M=64,N=1024,K=64 NN GEMMs. grid (16, 24)
// ===========================================================================
__global__ void __launch_bounds__(256)
trio_k(const float* __restrict__ CH1, const float* __restrict__ CH2,
       const float* __restrict__ G12,
       const float* __restrict__ x1, const float* __restrict__ x2,
       float* __restrict__ CH1O, float* __restrict__ CH2O, float* __restrict__ PP)
{
    __shared__ float As[16][68];
    __shared__ float Bs[16][68];
    const int tid = threadIdx.x;
    const int z = blockIdx.y, pair = z >> 3, b = z & 7;
    const int n0 = blockIdx.x * 64;
    const float* Ab = (pair == 0 ? CH1 : pair == 1 ? CH2 : G12) + (long)b * 4096;
    const float* Bb = (pair == 0 ? x1 : x2) + (long)b * 65536;
    float* Cb = (pair == 0 ? CH1O : pair == 1 ? CH2O : PP) + (long)b * 65536;
    const int rowt = (tid >> 4) * 4, colt = (tid & 15) * 4;
    float acc[4][4] = {};

    for (int k0 = 0; k0 < 64; k0 += 16) {
        {
            int r = tid >> 2, c = (tid & 3) * 4;
            float4 av = *(const float4*)(Ab + r * 64 + k0 + c);
            As[c+0][r]=av.x; As[c+1][r]=av.y; As[c+2][r]=av.z; As[c+3][r]=av.w;
        }
        {
            int kr = tid >> 4, nc = (tid & 15) * 4;
            float4 bv = *(const float4*)(Bb + (long)(k0 + kr) * 1024 + n0 + nc);
            *(float4*)&Bs[kr][nc] = bv;
        }
        __syncthreads();
#pragma unroll
        for (int kk = 0; kk < 16; kk++) {
            float4 a = *(const float4*)&As[kk][rowt];
            float4 bq = *(const float4*)&Bs[kk][colt];
            float ra[4] = {a.x,a.y,a.z,a.w}, rb[4] = {bq.x,bq.y,bq.z,bq.w};
#pragma unroll
            for (int i = 0; i < 4; i++)
#pragma unroll
                for (int j = 0; j < 4; j++) acc[i][j] += ra[i] * rb[j];
        }
        __syncthreads();
    }
#pragma unroll
    for (int i = 0; i < 4; i++)
        *(float4*)(Cb + (long)(rowt + i) * 1024 + n0 + colt) =
            make_float4(acc[i][0], acc[i][1], acc[i][2], acc[i][3]);
}

// ===========================================================================
// rowsumgram: blocks 0..15 = rowsums + zero ME; blocks 16..207 = gramA splits.
// ===========================================================================
__global__ void __launch_bounds__(256)
rowsumgram_k(const float* __restrict__ x1, const float* __restrict__ x2,
             float* __restrict__ r, unsigned* __restrict__ ME, float* __restrict__ P)
{
    if (blockIdx.x < 16) {
        int gid = blockIdx.x * 256 + threadIdx.x;
        for (int i = gid; i < 16384; i += 4096) ME[i] = 0u;

        int which = blockIdx.x >> 3, b = blockIdx.x & 7;
        const float* xb = (which ? x2 : x1) + (long)b * 65536;
        int w = threadIdx.x >> 5, lane = threadIdx.x & 31;
        for (int rr = w * 8; rr < w * 8 + 8; rr++) {
            float s = 0.f;
            for (int p = lane; p < 1024; p += 32) s += xb[rr * 1024 + p];
#pragma unroll
            for (int o = 16; o; o >>= 1) s += __shfl_xor_sync(0xffffffffu, s, o);
            if (lane == 0) r[which * 512 + b * 64 + rr] = s;
        }
        return;
    }

    __shared__ float Xs[16][68], Ys[16][68];
    const int tid = threadIdx.x;
    const int blk = blockIdx.x - 16;          // 0..191
    const int split = blk & 7, pz = blk >> 3; // pz 0..23
    const int pair = pz >> 3, b = pz & 7;
    const float* Xb = ((pair == 1) ? x2 : x1) + (long)b * 65536;
    const float* Yb = ((pair == 0) ? x1 : x2) + (long)b * 65536;
    const int kbase = split * 128;
    const int rowt = (tid >> 4) * 4, colt = (tid & 15) * 4;
    const int rr = tid >> 2, cc = (tid & 3) * 4;
    float acc[4][4] = {};

    for (int k0 = kbase; k0 < kbase + 128; k0 += 16) {
        float4 xv = *(const float4*)(Xb + (long)rr * 1024 + k0 + cc);
        float4 yv = *(const float4*)(Yb + (long)rr * 1024 + k0 + cc);
        Xs[cc+0][rr]=xv.x; Xs[cc+1][rr]=xv.y; Xs[cc+2][rr]=xv.z; Xs[cc+3][rr]=xv.w;
        Ys[cc+0][rr]=yv.x; Ys[cc+1][rr]=yv.y; Ys[cc+2][rr]=yv.z; Ys[cc+3][rr]=yv.w;
        __syncthreads();
#pragma unroll
        for (int kk = 0; kk < 16; kk++) {
            float4 a = *(const float4*)&Xs[kk][rowt];
            float4 bq = *(const float4*)&Ys[kk][colt];
            float ra[4]={a.x,a.y,a.z,a.w}, rb[4]={bq.x,bq.y,bq.z,bq.w};
#pragma unroll
            for (int i = 0; i < 4; i++)
#pragma unroll
                for (int j = 0; j < 4; j++) acc[i][j] += ra[i] * rb[j];
        }
        __syncthreads();
    }
    float* Pp = P + ((long)pz * 8 + split) * 4096;
#pragma unroll
    for (int i = 0; i < 4; i++)
        *(float4*)(Pp + (rowt + i) * 64 + colt) =
            make_float4(acc[i][0], acc[i][1], acc[i][2], acc[i][3]);
}

__global__ void reduceA_k(const float* __restrict__ P, float* __restrict__ O)
{
    int idx = blockIdx.x * 256 + threadIdx.x;   // < 98304
    int pz = idx >> 12, e = idx & 4095;
    float s = 0.f;
#pragma unroll
    for (int k = 0; k < 8; k++) s += P[((long)pz * 8 + k) * 4096 + e];
    O[idx] = s;
}

// Direct gram (no split): grid (1, batch), M=N=64, writes C[b*4096]
__global__ void __launch_bounds__(256)
gram_k(const float* __restrict__ X, const float* __restrict__ Y,
       float* __restrict__ P, int K, int klen, long sX, long sY)
{
    __shared__ float Xs[16][68], Ys[16][68];
    const int tid = threadIdx.x;
    const float* Xb = X + (long)blockIdx.y * sX;
    const float* Yb = Y + (long)blockIdx.y * sY;
    const int kbase = blockIdx.x * klen;
    const int rowt = (tid >> 4) * 4, colt = (tid & 15) * 4;
    const int r = tid >> 2, c = (tid & 3) * 4;
    float acc[4][4] = {};

    for (int k0 = kbase; k0 < kbase + klen; k0 += 16) {
        float4 xv = *(const float4*)(Xb + (long)r * K + k0 + c);
        float4 yv = *(const float4*)(Yb + (long)r * K + k0 + c);
        Xs[c+0][r]=xv.x; Xs[c+1][r]=xv.y; Xs[c+2][r]=xv.z; Xs[c+3][r]=xv.w;
        Ys[c+0][r]=yv.x; Ys[c+1][r]=yv.y; Ys[c+2][r]=yv.z; Ys[c+3][r]=yv.w;
        __syncthreads();
#pragma unroll
        for (int kk = 0; kk < 16; kk++) {
            float4 a = *(const float4*)&Xs[kk][rowt];
            float4 bq = *(const float4*)&Ys[kk][colt];
            float ra[4]={a.x,a.y,a.z,a.w}, rb[4]={bq.x,bq.y,bq.z,bq.w};
#pragma unroll
            for (int i = 0; i < 4; i++)
#pragma unroll
                for (int j = 0; j < 4; j++) acc[i][j] += ra[i] * rb[j];
        }
        __syncthreads();
    }
    float* Pp = P + ((long)blockIdx.y * gridDim.x + blockIdx.x) * 4096;
#pragma unroll
    for (int i = 0; i < 4; i++)
        *(float4*)(Pp + (rowt + i) * 64 + colt) =
            make_float4(acc[i][0], acc[i][1], acc[i][2], acc[i][3]);
}

// ===========================================================================
// smm / smm128
// ===========================================================================
template<int M, int N, int K, bool BT>
__device__ __forceinline__ void smm(const float* __restrict__ A, int lda,
                                    const float* __restrict__ B, int ldb,
                                    float* __restrict__ C, int ldc,
                                    const float* __restrict__ bias,
                                    const float* __restrict__ rscale, int t)
{
    constexpr int RM = M / 16, RN = N / 16;
    const int r0 = (t >> 4) * RM, c0 = (t & 15) * RN;
    float acc[RM][RN];
#pragma unroll
    for (int i = 0; i < RM; i++) {
        float bv = bias ? bias[r0 + i] : 0.f;
#pragma unroll
        for (int j = 0; j < RN; j++) acc[i][j] = bv;
    }
#pragma unroll 4
    for (int k = 0; k < K; k++) {
        float a[RM], b[RN];
#pragma unroll
        for (int i = 0; i < RM; i++) a[i] = A[(r0 + i) * lda + k];
#pragma unroll
        for (int j = 0; j < RN; j++) b[j] = BT ? B[(c0 + j) * ldb + k] : B[k * ldb + c0 + j];
#pragma unroll
        for (int i = 0; i < RM; i++)
#pragma unroll
            for (int j = 0; j < RN; j++) acc[i][j] += a[i] * b[j];
    }
#pragma unroll
    for (int i = 0; i < RM; i++) {
        float sc = rscale ? rscale[r0 + i] : 1.f;
#pragma unroll
        for (int j = 0; j < RN; j++) C[(r0 + i) * ldc + c0 + j] = acc[i][j] * sc;
    }
}

template<int M, int N, int K, bool BT>
__device__ __forceinline__ void smm128(const float* __restrict__ A, int lda,
                                       const float* __restrict__ B, int ldb,
                                       float* __restrict__ C, int ldc,
                                       const float* __restrict__ bias,
                                       const float* __restrict__ rscale, int t)
{
    constexpr int RM = M / 8, RN = N / 16;
    const int r0 = (t >> 4) * RM, c0 = (t & 15) * RN;
    float acc[RM][RN];
#pragma unroll
    for (int i = 0; i < RM; i++) {
        float bv = bias ? bias[r0 + i] : 0.f;
#pragma unroll
        for (int j = 0; j < RN; j++) acc[i][j] = bv;
    }
#pragma unroll 4
    for (int k = 0; k < K; k++) {
        float a[RM], b[RN];
#pragma unroll
        for (int i = 0; i < RM; i++) a[i] = A[(r0 + i) * lda + k];
#pragma unroll
        for (int j = 0; j < RN; j++) b[j] = BT ? B[(c0 + j) * ldb + k] : B[k * ldb + c0 + j];
#pragma unroll
        for (int i = 0; i < RM; i++)
#pragma unroll
            for (int j = 0; j < RN; j++) acc[i][j] += a[i] * b[j];
    }
#pragma unroll
    for (int i = 0; i < RM; i++) {
        float sc = rscale ? rscale[r0 + i] : 1.f;
#pragma unroll
        for (int j = 0; j < RN; j++) C[(r0 + i) * ldc + c0 + j] = acc[i][j] * sc;
    }
}

// Cd = Mb(32x64,ld68) * Wd^T + bd u^T + u bd^T + 1024 bd bd^T  (128 threads)
__device__ __forceinline__ void cd_stage(const float* __restrict__ Mb,
                                         const float* __restrict__ Wd,
                                         float* __restrict__ Cd,
                                         const float* __restrict__ bd,
                                         const float* __restrict__ u, int t)
{
    const int r0 = (t >> 4) * 4, c0 = (t & 15) * 2;
    float acc[4][2] = {};
#pragma unroll 4
    for (int k = 0; k < 64; k++) {
        float a[4], b[2];
#pragma unroll
        for (int i = 0; i < 4; i++) a[i] = Mb[(r0 + i) * 68 + k];
#pragma unroll
        for (int j = 0; j < 2; j++) b[j] = Wd[(c0 + j) * 64 + k];
#pragma unroll
        for (int i = 0; i < 4; i++)
#pragma unroll
            for (int j = 0; j < 2; j++) acc[i][j] += a[i] * b[j];
    }
#pragma unroll
    for (int i = 0; i < 4; i++) {
        int d = r0 + i;
#pragma unroll
        for (int j = 0; j < 2; j++) {
            int e = c0 + j;
            Cd[d * 36 + e] = acc[i][j] + bd[d]*u[e] + bd[e]*u[d] + 1024.f*bd[d]*bd[e];
        }
    }
}

// ===========================================================================
// Fused channel path: 16 blocks = (batch, dir). Each block does one direction
// (LC/Cd computed redundantly per block; halves the per-SM serial work).
// ===========================================================================
__global__ void __launch_bounds__(256)
chan_fused_k(const float* __restrict__ X1C_g, const float* __restrict__ X2C_g,
             const float* __restrict__ rsum,
             const float* __restrict__ w_down, const float* __restrict__ b_down,
             const float* __restrict__ w_up, const float* __restrict__ b_up,
             float* __restrict__ CH1_g, float* __restrict__ CH2_g)
{
    extern __shared__ float sm[];
    float* A   = sm;              // 64x68  X1C -> U
    float* Bf  = A   + 4352;      // 64x68  X2C
    float* LC  = Bf  + 4352;      // 64x68
    float* E   = LC  + 4352;      // 64x68
    float* Wd  = E   + 4352;      // 32x64
    float* Wu  = Wd  + 2048;      // 64x32
    float* Mb1 = Wu  + 2048;      // 32x68
    float* Mb2 = Mb1 + 2176;      // 32x68
    float* C1d = Mb2 + 2176;      // 32x36
    float* C2d = C1d + 1152;
    float* LCD = C2d + 1152;
    float* Ad  = LCD + 1152;      // 32x36 (this dir's softmaxed LCD)
    float* TT  = Ad  + 1152;      // 64x36
    float* bd  = TT  + 2304;      // 32
    float* bu  = bd  + 32;        // 64
    float* u1  = bu  + 64;        // 32
    float* u2  = u1  + 32;        // 32
    float* st  = u2  + 32;        // 128: max, inv

    const int bi = blockIdx.x >> 1, dir = blockIdx.x & 1;
    const int t = threadIdx.x;
    const bool h0 = t < 128;
    const int ht = h0 ? t : t - 128;

    for (int i = t; i < 4096; i += 256) {
        A [(i >> 6) * 68 + (i & 63)] = X1C_g[bi * 4096 + i];
        Bf[(i >> 6) * 68 + (i & 63)] = X2C_g[bi * 4096 + i];
    }
    for (int i = t; i < 2048; i += 256) { Wd[i] = w_down[i]; Wu[i] = w_up[i]; }
    if (t < 32) bd[t] = b_down[t];
    if (t < 64) bu[t] = b_up[t];
    __syncthreads();

    if (t < 64) {
        int d = t & 31, which = t >> 5;
        const float* r = rsum + which * 512 + bi * 64;
        float s = 0.f;
        for (int c = 0; c < 64; c++) s += Wd[d * 64 + c] * r[c];
        (which ? u2 : u1)[d] = s;
    }
    __syncthreads();

    // Cd pair (both needed for LCD), halves in parallel
    if (h0) smm128<32, 64, 64, false>(Wd, 64, A, 68, Mb1, 68, nullptr, nullptr, ht);
    else    smm128<32, 64, 64, false>(Wd, 64, Bf, 68, Mb2, 68, nullptr, nullptr, ht);
    __syncthreads();
    if (h0) cd_stage(Mb1, Wd, C1d, bd, u1, ht);
    else    cd_stage(Mb2, Wd, C2d, bd, u2, ht);
    __syncthreads();

    // LC full block
    smm<64, 64, 64, false>(A, 68, Bf, 68, LC, 68, nullptr, nullptr, t);
    __syncthreads();

    // this-dir stats (t<64) || LCD (t>=128)
    if (t < 64) {
        float m = -3.4e38f;
        if (dir == 0) {
            for (int j = 0; j < 64; j++) m = fmaxf(m, LC[t * 68 + j]);
            float s = 0.f;
            for (int j = 0; j < 64; j++) s += __expf(LC[t * 68 + j] - m);
            st[t] = m; st[64 + t] = 1.f / s;
        } else {
            for (int j = 0; j < 64; j++) m = fmaxf(m, LC[j * 68 + t]);
            float s = 0.f;
            for (int j = 0; j < 64; j++) s += __expf(LC[j * 68 + t] - m);
            st[t] = m; st[64 + t] = 1.f / s;
        }
    } else if (t >= 128) {
        smm128<32, 32, 32, false>(C1d, 36, C2d, 36, LCD, 36, nullptr, nullptr, ht);
    }
    __syncthreads();

    // E (t>=64, 192 threads) || this-dir LCD softmax -> Ad (t<32)
    if (t < 32) {
        float m = -3.4e38f;
        if (dir == 0) {
            for (int j = 0; j < 32; j++) m = fmaxf(m, LCD[t * 36 + j]);
            float s = 0.f;
            for (int j = 0; j < 32; j++) s += __expf(LCD[t * 36 + j] - m);
            float inv = 1.f / s;
            for (int j = 0; j < 32; j++) Ad[t * 36 + j] = __expf(LCD[t * 36 + j] - m) * inv;
        } else {
            for (int j = 0; j < 32; j++) m = fmaxf(m, LCD[j * 36 + t]);
            float s = 0.f;
            for (int j = 0; j < 32; j++) s += __expf(LCD[j * 36 + t] - m);
            float inv = 1.f / s;
            for (int j = 0; j < 32; j++) Ad[t * 36 + j] = __expf(LCD[j * 36 + t] - m) * inv;
        }
    } else if (t >= 64) {
        for (int o = t - 64; o < 4096; o += 192) {
            int i = o >> 6, j = o & 63;
            E[i * 68 + j] = dir == 0 ? __expf(LC[i * 68 + j] - st[i])
                                     : __expf(LC[j * 68 + i] - st[i]);
        }
    }
    __syncthreads();

    // ConvUp: TT = Wu Ad + bu ; U[m][i] = bu[m] + sum_k Wu[m][k] TT[i][k] -> A
    smm<64, 32, 32, false>(Wu, 32, Ad, 36, TT, 36, bu, nullptr, t);
    __syncthreads();
    smm<64, 64, 32, true >(Wu, 32, TT, 36, A, 68, bu, nullptr, t);
    __syncthreads();

    // CH = diag(inv) E U^T -> global
    float* CHo = (dir == 0 ? CH1_g : CH2_g) + bi * 4096;
    smm<64, 64, 64, true>(E, 68, A, 68, CHo, 64, nullptr, st + 64, t);
}

// ===========================================================================
// Merged LFD softmaxes: blocks 0..2047 row softmax; 2048..2079 col-T. N=256.
// ===========================================================================
__global__ void softLFD_k(const float* __restrict__ L,
                          float* __restrict__ AFD12, float* __restrict__ AFD21T)
{
    if (blockIdx.x < 2048) {
        long row = blockIdx.x;
        const float* p = L + row * 256;
        float* q = AFD12 + row * 256;
        int t = threadIdx.x;
        __shared__ float sh[8];

        float m = -3.4e38f;
        for (int i = t; i < 256; i += 256) m = fmaxf(m, p[i]);
#pragma unroll
        for (int o = 16; o; o >>= 1) m = fmaxf(m, __shfl_xor_sync(0xffffffffu, m, o));
        if ((t & 31) == 0) sh[t >> 5] = m;
        __syncthreads();
        float mm = sh[0];
#pragma unroll
        for (int w = 1; w < 8; w++) mm = fmaxf(mm, sh[w]);
        __syncthreads();

        float s = __expf(p[t] - mm);
        float sv = s;
#pragma unroll
        for (int o = 16; o; o >>= 1) s += __shfl_xor_sync(0xffffffffu, s, o);
        if ((t & 31) == 0) sh[t >> 5] = s;
        __syncthreads();
        float ss = 0.f;
#pragma unroll
        for (int w = 0; w < 8; w++) ss += sh[w];
        q[t] = sv / ss;
    } else {
        int blk = blockIdx.x - 2048;
        int cc = threadIdx.x & 63;
        int kg = threadIdx.x >> 6;
        int bi = blk >> 2;
        int i  = (blk & 3) * 64 + cc;
        const float* Lb = L      + (long)bi * 65536;
        float*       Ab = AFD21T + (long)bi * 65536;
        __shared__ float red[4][64];

        float m = -3.4e38f;
        for (int k = kg; k < 256; k += 4) m = fmaxf(m, Lb[k * 256 + i]);
        red[kg][cc] = m;
        __syncthreads();
        m = fmaxf(fmaxf(red[0][cc], red[1][cc]), fmaxf(red[2][cc], red[3][cc]));
        __syncthreads();

        float s = 0.f;
        for (int k = kg; k < 256; k += 4) s += __expf(Lb[k * 256 + i] - m);
        red[kg][cc] = s;
        __syncthreads();
        s = red[0][cc] + red[1][cc] + red[2][cc] + red[3][cc];
        float inv = 1.f / s;

        for (int k = kg; k < 256; k += 4)
            Ab[k * 256 + i] = __expf(Lb[k * 256 + i] - m) * inv;
    }
}

// ===========================================================================
// ypair: Y1 = AFD12 @ Z1^T ; Y2 = AFD21T^T @ Z2^T. grid (4, 8, 2).
// ===========================================================================
__global__ void __launch_bounds__(256)
ypair_k(const float* __restrict__ AFD12, const float* __restrict__ AFD21T,
        const float* __restrict__ Z1, const float* __restrict__ Z2,
        float* __restrict__ Y1, float* __restrict__ Y2)
{
    __shared__ float As[16][68];
    __shared__ float Bs[16][68];
    const int tid = threadIdx.x;
    const int m0 = blockIdx.x * 64, b = blockIdx.y, dir = blockIdx.z;
    const float* Ab = (dir ? AFD21T : AFD12) + (long)b * 65536;
    const float* Zb = (dir ? Z2 : Z1) + (long)b * 16384;
    float* Yb = (dir ? Y2 : Y1) + (long)b * 16384;
    const int rowt = (tid >> 4) * 4, colt = (tid & 15) * 4;
    float acc[4][4] = {};

    for (int k0 = 0; k0 < 256; k0 += 16) {
        if (dir == 0) {
            int r = tid >> 2, c = (tid & 3) * 4;
            float4 av = *(const float4*)(Ab + (long)(m0 + r) * 256 + k0 + c);
            As[c+0][r]=av.x; As[c+1][r]=av.y; As[c+2][r]=av.z; As[c+3][r]=av.w;
        } else {
            int kr = tid >> 4, mc = (tid & 15) * 4;
            *(float4*)&As[kr][mc] = *(const float4*)(Ab + (long)(k0 + kr) * 256 + m0 + mc);
        }
        {
            int r = tid >> 2, c = (tid & 3) * 4;
            float4 bv = *(const float4*)(Zb + (long)r * 256 + k0 + c);
            Bs[c+0][r]=bv.x; Bs[c+1][r]=bv.y; Bs[c+2][r]=bv.z; Bs[c+3][r]=bv.w;
        }
        __syncthreads();
#pragma unroll
        for (int kk = 0; kk < 16; kk++) {
            float4 a = *(const float4*)&As[kk][rowt];
            float4 bq = *(const float4*)&Bs[kk][colt];
            float ra[4]={a.x,a.y,a.z,a.w}, rb[4]={bq.x,bq.y,bq.z,bq.w};
#pragma unroll
            for (int i = 0; i < 4; i++)
#pragma unroll
                for (int j = 0; j < 4; j++) acc[i][j] += ra[i] * rb[j];
        }
        __syncthreads();
    }
#pragma unroll
    for (int i = 0; i < 4; i++)
        *(float4*)(Yb + (long)(m0 + rowt + i) * 64 + colt) =
            make_float4(acc[i][0], acc[i][1], acc[i][2], acc[i][3]);
}

// ===========================================================================
// av kernels: threshold exp + per-kk-row liveness (double-buffered flags).
// ===========================================================================
__global__ void __launch_bounds__(256)
av_row_k(const float* __restrict__ L, const float* __restrict__ W,
         const unsigned* __restrict__ RSME, float* __restrict__ O)
{
    __shared__ float Ls[16][68], Ws[16][68];
    __shared__ float smx[64], spart[256], sinv[64];
    __shared__ int sflag[2][16];
    const int tid = threadIdx.x;
    const int b = blockIdx.y, m0 = blockIdx.x * 64;
    if (tid < 64) smx[tid] = fdec(RSME[b * 1024 + m0 + tid]);
    if (tid < 32) sflag[tid >> 4][tid & 15] = 0;
    __syncthreads();
    const float* Lb = L + (long)b * 1048576;
    const float* Wb = W + (long)b * 65536;
    const int rowt = (tid >> 4) * 4, colt = (tid & 15) * 4;
    const int r = tid >> 2, c = (tid & 3) * 4;
    const int kr = tid >> 4, nc = (tid & 15) * 4;
    float acc[4][4] = {};
    float psum = 0.f;
    const float mr = smx[r], thr = mr - 20.f;

    for (int k0 = 0; k0 < 1024; k0 += 16) {
        const int p = (k0 >> 4) & 1;
        float4 v = *(const float4*)(Lb + (long)(m0 + r) * 1024 + k0 + c);
        float4 e = {0.f, 0.f, 0.f, 0.f};
        if (v.x > thr || v.y > thr || v.z > thr || v.w > thr) {
            e.x = __expf(v.x - mr); e.y = __expf(v.y - mr);
            e.z = __expf(v.z - mr); e.w = __expf(v.w - mr);
            psum += e.x + e.y + e.z + e.w;
            if (e.x > 0.f) atomicOr(&sflag[p][c + 0], 1);
            if (e.y > 0.f) atomicOr(&sflag[p][c + 1], 1);
            if (e.z > 0.f) atomicOr(&sflag[p][c + 2], 1);
            if (e.w > 0.f) atomicOr(&sflag[p][c + 3], 1);
        }
        Ls[c+0][r] = e.x; Ls[c+1][r] = e.y; Ls[c+2][r] = e.z; Ls[c+3][r] = e.w;
        *(float4*)&Ws[kr][nc] = *(const float4*)(Wb + (long)(k0 + kr) * 64 + nc);
        __syncthreads();
        int mask = 0;
#pragma unroll
        for (int kk = 0; kk < 16; kk++) mask |= (sflag[p][kk] ? (1 << kk) : 0);
        if (tid < 16) sflag[p ^ 1][tid] = 0;   // reset other buffer for next chunk
        if (mask) {
#pragma unroll
            for (int kk = 0; kk < 16; kk++) {
                if ((mask >> kk) & 1) {
                    float4 a = *(const float4*)&Ls[kk][rowt];
                    float4 w = *(const float4*)&Ws[kk][colt];
                    float ra[4]={a.x,a.y,a.z,a.w}, rb[4]={w.x,w.y,w.z,w.w};
#pragma unroll
                    for (int i = 0; i < 4; i++)
#pragma unroll
                        for (int j = 0; j < 4; j++) acc[i][j] += ra[i] * rb[j];
                }
            }
        }
        __syncthreads();
    }
    spart[tid] = psum;
    __syncthreads();
    if (tid < 64)
        sinv[tid] = 1.f / (spart[4*tid] + spart[4*tid+1] + spart[4*tid+2] + spart[4*tid+3]);
    __syncthreads();

    float* Ob = O + (long)b * 65536;
#pragma unroll
    for (int i = 0; i < 4; i++) {
        float sc = sinv[rowt + i];
        *(float4*)(Ob + (long)(m0 + rowt + i) * 64 + colt) =
            make_float4(acc[i][0]*sc, acc[i][1]*sc, acc[i][2]*sc, acc[i][3]*sc);
    }
}

__global__ void __launch_bounds__(256)
av_col_k(const float* __restrict__ L, const float* __restrict__ W,
         const unsigned* __restrict__ CSME, float* __restrict__ O)
{
    __shared__ float Ls[16][68], Ws[16][68];
    __shared__ float smx[64], scs[16][64], sinv[64];
    __shared__ int sflag[2][16];
    const int tid = threadIdx.x;
    const int b = blockIdx.y, m0 = blockIdx.x * 64;
    if (tid < 64) smx[tid] = fdec(CSME[b * 1024 + m0 + tid]);
    if (tid < 32) sflag[tid >> 4][tid & 15] = 0;
    __syncthreads();
    const float* Lb = L + (long)b * 1048576;
    const float* Wb = W + (long)b * 65536;
    const int rowt = (tid >> 4) * 4, colt = (tid & 15) * 4;
    const int kr = tid >> 4, mc = (tid & 15) * 4;
    float acc[4][4] = {};
    float ps[4] = {0.f, 0.f, 0.f, 0.f};
    const float m0f = smx[mc], m1f = smx[mc+1], m2f = smx[mc+2], m3f = smx[mc+3];

    for (int k0 = 0; k0 < 1024; k0 += 16) {
        const int p = (k0 >> 4) & 1;
        float4 v = *(const float4*)(Lb + (long)(k0 + kr) * 1024 + m0 + mc);
        float4 e = {0.f, 0.f, 0.f, 0.f};
        if (v.x > m0f - 20.f || v.y > m1f - 20.f || v.z > m2f - 20.f || v.w > m3f - 20.f) {
            e.x = (v.x > m0f - 20.f) ? __expf(v.x - m0f) : 0.f;
            e.y = (v.y > m1f - 20.f) ? __expf(v.y - m1f) : 0.f;
            e.z = (v.z > m2f - 20.f) ? __expf(v.z - m2f) : 0.f;
            e.w = (v.w > m3f - 20.f) ? __expf(v.w - m3f) : 0.f;
            ps[0] += e.x; ps[1] += e.y; ps[2] += e.z; ps[3] += e.w;
            atomicOr(&sflag[p][kr], 1);
        }
        *(float4*)&Ls[kr][mc] = e;
        *(float4*)&Ws[kr][mc] = *(const float4*)(Wb + (long)(k0 + kr) * 64 + mc);
        __syncthreads();
        int mask = 0;
#pragma unroll
        for (int kk = 0; kk < 16; kk++) mask |= (sflag[p][kk] ? (1 << kk) : 0);
        if (tid < 16) sflag[p ^ 1][tid] = 0;
        if (mask) {
#pragma unroll
            for (int kk = 0; kk < 16; kk++) {
                if ((mask >> kk) & 1) {
                    float4 a = *(const float4*)&Ls[kk][rowt];
                    float4 w = *(const float4*)&Ws[kk][colt];
                    float ra[4]={a.x,a.y,a.z,a.w}, rb[4]={w.x,w.y,w.z,w.w};
#pragma unroll
                    for (int i = 0; i < 4; i++)
#pragma unroll
                        for (int j = 0; j < 4; j++) acc[i][j] += ra[i] * rb[j];
                }
            }
        }
        __syncthreads();
    }
#pragma unroll
    for (int j = 0; j < 4; j++) scs[kr][mc + j] = ps[j];
    __syncthreads();
    if (tid < 64) {
        float s = 0.f;
#pragma unroll
        for (int k = 0; k < 16; k++) s += scs[k][tid];
        sinv[tid] = 1.f / s;
    }
    __syncthreads();

    float* Ob = O + (long)b * 65536;
#pragma unroll
    for (int i = 0; i < 4; i++) {
        float sc = sinv[rowt + i];
        *(float4*)(Ob + (long)(m0 + rowt + i) * 64 + colt) =
            make_float4(acc[i][0]*sc, acc[i][1]*sc, acc[i][2]*sc, acc[i][3]*sc);
    }
}

// ---------------------------------------------------------------------------
// Keys cubic + merged resampling
// ---------------------------------------------------------------------------
__device__ __forceinline__ float keys_cubic(float x)
{
    x = fabsf(x);
    if (x < 1.f) return ((1.5f * x - 2.5f) * x) * x + 1.f;
    if (x < 2.f) return ((-0.5f * x + 2.5f) * x - 4.f) * x + 2.f;
    return 0.f;
}

__global__ void resample_k(const float* __restrict__ x1, const float* __restrict__ x2,
                           float* __restrict__ y1, float* __restrict__ y2,
                           float* __restrict__ Z1, float* __restrict__ Z2)
{
    int gidx = blockIdx.x * 256 + threadIdx.x;
    if (gidx < 262144) {
        const float* x = gidx < 131072 ? x1 : x2;
        float* y = gidx < 131072 ? y1 : y2;
        int idx = gidx & 131071;
        int ox = idx & 15;
        int oy = (idx >> 4) & 15;
        int bc = idx >> 8;

        int jy0 = 2 * oy - 3, jx0 = 2 * ox - 3;
        float wy[8], wx[8];
        float sy = 0.f, sx = 0.f;
#pragma unroll
        for (int t = 0; t < 8; t++) {
            float w = keys_cubic(fabsf(3.5f - t) * 0.5f);
            int jy = jy0 + t;
            wy[t] = (jy >= 0 && jy < 32) ? w : 0.f; sy += wy[t];
            int jx = jx0 + t;
            wx[t] = (jx >= 0 && jx < 32) ? w : 0.f; sx += wx[t];
        }
        float iy = 1.f / sy, ix = 1.f / sx;
#pragma unroll
        for (int t = 0; t < 8; t++) { wy[t] *= iy; wx[t] *= ix; }

        const float* src = x + (long)bc * 1024;
        float acc = 0.f;
#pragma unroll
        for (int t = 0; t < 8; t++) {
            int jy = min(max(jy0 + t, 0), 31);
            float r = 0.f;
#pragma unroll
            for (int u = 0; u < 8; u++) {
                int jx = min(max(jx0 + u, 0), 31);
                r += wx[u] * src[jy * 32 + jx];
            }
            acc += wy[t] * r;
        }
        y[idx] = acc;
    } else if (gidx < 524288) {
        int g2 = gidx - 262144;
        const float* x = g2 < 131072 ? x1 : x2;
        float* Z = g2 < 131072 ? Z1 : Z2;
        int idx = g2 & 131071;
        int j = idx & 255;
        int c = (idx >> 8) & 63;
        int b = idx >> 14;
        const float* xr = x + (long)b * 65536 + (long)c * 1024;

        float acc = 0.f;
        int Ilo = max(0, 4 * j - 8), Ihi = min(1023, 4 * j + 10);
        for (int I = Ilo; I <= Ihi; I++) {
            float sf = (I + 0.5f) * 0.25f - 0.5f;
            float fl = floorf(sf);
            float f  = sf - fl;
            int base = (int)fl - 1;
            int tt = j - base;
            if (tt < 0 || tt > 3) continue;
            float tot = 0.f, wsel = 0.f;
#pragma unroll
            for (int t = 0; t < 4; t++) {
                float w = keys_cubic(f + 1.f - t);
                int jj = base + t;
                if (jj < 0 || jj >= 256) w = 0.f;
                tot += w;
                if (t == tt) wsel = w;
            }
            acc += xr[I] * (wsel / tot);
        }
        Z[idx] = acc;
    }
}

// W[b][I][c] = sum_t w_t(I) Y[b][base+t][c]
__global__ void upapply2_k(const float* __restrict__ Y1, const float* __restrict__ Y2,
                           float* __restrict__ W1, float* __restrict__ W2)
{
    int gidx = blockIdx.x * 256 + threadIdx.x;
    if (gidx >= 1048576) return;
    const float* Y = gidx < 524288 ? Y1 : Y2;
    float* Wo = gidx < 524288 ? W1 : W2;
    int idx = gidx & 524287;
    int c = idx & 63;
    int I = (idx >> 6) & 1023;
    int b = idx >> 16;

    float sf = (I + 0.5f) * 0.25f - 0.5f;
    float fl = floorf(sf);
    float f  = sf - fl;
    int base = (int)fl - 1;
    float w[4], tot = 0.f;
#pragma unroll
    for (int t = 0; t < 4; t++) {
        float ww = keys_cubic(f + 1.f - t);
        int jj = base + t;
        if (jj < 0 || jj >= 256) ww = 0.f;
        w[t] = ww; tot += ww;
    }
    float inv = 1.f / tot;
    const float* Yb = Y + (long)b * 16384;
    float acc = 0.f;
#pragma unroll
    for (int t = 0; t < 4; t++)
        if (w[t] != 0.f) acc += w[t] * Yb[(base + t) * 64 + c];
    Wo[idx] = acc * inv;
}

// ---------------------------------------------------------------------------
// BN stats (grid 256)
// ---------------------------------------------------------------------------
__global__ void bn_all_k(const float* __restrict__ CH1O, const float* __restrict__ CH2O,
                         const float* __restrict__ HW1OT, const float* __restrict__ HW2OT,
                         float* __restrict__ mv)
{
    int which = blockIdx.x >> 6, c = blockIdx.x & 63;
    const float* T = which == 0 ? CH1O : which == 1 ? CH2O : which == 2 ? HW1OT : HW2OT;
    bool tr = which >= 2;
    int t = threadIdx.x;
    float s = 0.f, s2 = 0.f;
    for (int i = t; i < 8192; i += 256) {
        float v = tr ? T[(long)(i >> 10) * 65536 + (long)(i & 1023) * 64 + c]
                     : T[(long)(i >> 10) * 65536 + c * 1024 + (i & 1023)];
        s += v; s2 += v * v;
    }
    __shared__ float sh1[8], sh2[8];
#pragma unroll
    for (int o = 16; o; o >>= 1) {
        s  += __shfl_xor_sync(0xffffffffu, s, o);
        s2 += __shfl_xor_sync(0xffffffffu, s2, o);
    }
    if ((t & 31) == 0) { sh1[t >> 5] = s; sh2[t >> 5] = s2; }
    __syncthreads();
    if (t == 0) {
        float ts = 0.f, ts2 = 0.f;
#pragma unroll
        for (int w = 0; w < 8; w++) { ts += sh1[w]; ts2 += sh2[w]; }
        float mean = ts * (1.f / 8192.f);
        float var  = ts2 * (1.f / 8192.f) - mean * mean;
        mv[which * 128 + c] = mean;
        mv[which * 128 + 64 + c] = fmaxf(var, 0.f);
    }
}

// ---------------------------------------------------------------------------
// Finalize
// ---------------------------------------------------------------------------
__global__ void finalize_k(const float* __restrict__ x1, const float* __restrict__ x2,
                           const float* __restrict__ ch1o, const float* __restrict__ ch2o,
                           const float* __restrict__ hw1t, const float* __restrict__ hw2t,
                           const float* __restrict__ mv,
                           const float* __restrict__ gamma, const float* __restrict__ beta,
                           float* __restrict__ out)
{
    int idx = blockIdx.x * 256 + threadIdx.x;
    if (idx >= 524288) return;
    int c = (idx >> 10) & 63;
    long hwi = ((long)(idx >> 16)) * 65536 + (long)(idx & 1023) * 64 + c;
    float g = gamma[c], be = beta[c];

    float xa = x1[idx], xb = x2[idx];

    float v, r;
    v = (ch1o[idx] - mv[c])       * rsqrtf(mv[64 + c]  + 1e-5f) * g + be + xa;
    r = fmaxf(v, 0.f);
    v = (hw1t[hwi] - mv[256 + c]) * rsqrtf(mv[320 + c] + 1e-5f) * g + be + xa;
    out[idx] = 0.5f * (r + fmaxf(v, 0.f));

    v = (ch2o[idx] - mv[128 + c]) * rsqrtf(mv[192 + c] + 1e-5f) * g + be + xb;
    r = fmaxf(v, 0.f);
    v = (hw2t[hwi] - mv[384 + c]) * rsqrtf(mv[448 + c] + 1e-5f) * g + be + xb;
    out[524288 + idx] = 0.5f * (r + fmaxf(v, 0.f));
}

// ===========================================================================
extern "C" void kernel_launch(void* const* d_in, const int* in_sizes, int n_in,
                              void* d_out, int out_size)
{
    const float* x1     = (const float*)d_in[0];
    const float* x2     = (const float*)d_in[1];
    const float* w_down = (const float*)d_in[2];
    const float* b_down = (const float*)d_in[3];
    const float* w_up   = (const float*)d_in[4];
    const float* b_up   = (const float*)d_in[5];
    const float* gamma  = (const float*)d_in[6];
    const float* beta   = (const float*)d_in[7];
    float* out = (float*)d_out;

    float* base = nullptr;
    cudaGetSymbolAddress((void**)&base, g_buf);

    float* LB = base;                      // [8,1024,1024]
    float* S  = base + 8ll * 1024 * 1024;
    float* X1C   = S; S += 32768;    // (X1C,X2C,G12 contiguous for reduceA)
    float* X2C   = S; S += 32768;
    float* G12   = S; S += 32768;
    float* GD    = S; S += 32768;
    float* CH1   = S; S += 32768;
    float* CH2   = S; S += 32768;
    float* CH1O  = S; S += 524288;
    float* CH2O  = S; S += 524288;
    float* XDN1  = S; S += 131072;
    float* XDN2  = S; S += 131072;
    float* PD    = S; S += 131072;
    float* LFD   = S; S += 524288;
    float* AFD12 = S; S += 524288;
    float* AFD21T= S; S += 524288;
    float* Z1    = S; S += 131072;
    float* Z2    = S; S += 131072;
    float* Y1    = S; S += 131072;
    float* Y2    = S; S += 131072;
    float* W1    = S; S += 524288;
    float* W2    = S; S += 524288;
    float* HW1OT = S; S += 524288;
    float* HW2OT = S; S += 524288;
    float* PP    = S; S += 524288;
    unsigned* RSME = (unsigned*)S; S += 8192;   // encoded maxes (RSME+CSME contiguous)
    unsigned* CSME = (unsigned*)S; S += 8192;
    float* R12   = S; S += 1024;
    float* PART  = S; S += 786432;
    float* MV    = S; S += 512;

    const int CHAN_SMEM = 33056 * 4;
    cudaFuncSetAttribute(chan_fused_k, cudaFuncAttributeMaxDynamicSharedMemorySize, CHAN_SMEM);

    // ---- grams + rowsums (one launch; also zeros the encoded max arrays) ----
    rowsumgram_k<<<208, 256>>>(x1, x2, R12, RSME, PART);
    reduceA_k<<<384, 256>>>(PART, X1C);           // X1C, X2C, G12

    // ---- fused channel path (16 blocks: batch x dir) ----
    chan_fused_k<<<16, 256, CHAN_SMEM>>>(X1C, X2C, R12, w_down, b_down, w_up, b_up, CH1, CH2);
    trio_k<<<dim3(16, 24), 256>>>(CH1, CH2, G12, x1, x2, CH1O, CH2O, PP);

    // ---- big logits (maxes folded into epilogue) ----
    lbgemm_k<<<dim3(16, 16, 8), 256>>>(x1, PP, LB, RSME, CSME);

    // ---- downsampled attention ----
    resample_k<<<2048, 256>>>(x1, x2, XDN1, XDN2, Z1, Z2);
    gram_k<<<dim3(1, 8), 256>>>(XDN1, XDN2, GD, 256, 256, 16384, 16384);
    launch_gemm64(false, false, GD, XDN2, PD, 64, 256, 64, 4096, 16384, 16384, 8);
    launch_gemm64(true,  false, XDN1, PD, LFD, 256, 256, 64, 16384, 16384, 65536, 8);
    softLFD_k<<<2080, 256>>>(LFD, AFD12, AFD21T);

    // ---- W = U (AFD (xU)^T) ----
    ypair_k<<<dim3(4, 8, 2), 256>>>(AFD12, AFD21T, Z1, Z2, Y1, Y2);
    upapply2_k<<<4096, 256>>>(Y1, Y2, W1, W2);

    // ---- fused softmax(L) @ W with sparsity skip ----
    av_row_k<<<dim3(16, 8), 256>>>(LB, W1, RSME, HW1OT);
    av_col_k<<<dim3(16, 8), 256>>>(LB, W2, CSME, HW2OT);

    // ---- BN + residual + relu + average ----
    bn_all_k<<<256, 256>>>(CH1O, CH2O, HW1OT, HW2OT, MV);
    finalize_k<<<2048, 256>>>(x1, x2, CH1O, CH2O, HW1OT, HW2OT, MV, gamma, beta, out);
}

// round 15
// speedup vs baseline: 1.1745x; 1.1745x over previous
#include <cuda_runtime.h>
#include <math.h>

// ---------------------------------------------------------------------------
// B=8, C=64, HW=1024, D=32.  10-launch pipeline.
// ---------------------------------------------------------------------------
__device__ float g_buf[17ll * 1024 * 1024];

__device__ __forceinline__ unsigned fenc(float f)
{
    unsigned b = __float_as_uint(f);
    return (b & 0x80000000u) ? ~b : (b | 0x80000000u);
}
__device__ __forceinline__ float fdec(unsigned u)
{
    return (u & 0x80000000u) ? __uint_as_float(u & 0x7FFFFFFFu)
                             : __uint_as_float(~u);
}

__device__ __forceinline__ float keys_cubic(float x)
{
    x = fabsf(x);
    if (x < 1.f) return ((1.5f * x - 2.5f) * x) * x + 1.f;
    if (x < 2.f) return ((-0.5f * x + 2.5f) * x - 4.f) * x + 2.f;
    return 0.f;
}

// ===========================================================================
// prep_k: blocks 0..15 rowsums + zero ME/MV; 16..207 gramA splits;
//         208..2255 resample (downsample + upsample-adjoint).
// ===========================================================================
__global__ void __launch_bounds__(256)
prep_k(const float* __restrict__ x1, const float* __restrict__ x2,
       float* __restrict__ r, unsigned* __restrict__ ME, float* __restrict__ MV,
       float* __restrict__ P,
       float* __restrict__ y1, float* __restrict__ y2,
       float* __restrict__ Z1, float* __restrict__ Z2)
{
    if (blockIdx.x < 16) {
        int gid = blockIdx.x * 256 + threadIdx.x;
        for (int i = gid; i < 16384; i += 4096) ME[i] = 0u;
        if (gid < 512) MV[gid] = 0.f;

        int which = blockIdx.x >> 3, b = blockIdx.x & 7;
        const float* xb = (which ? x2 : x1) + (long)b * 65536;
        int w = threadIdx.x >> 5, lane = threadIdx.x & 31;
        for (int rr = w * 8; rr < w * 8 + 8; rr++) {
            float s = 0.f;
            for (int p = lane; p < 1024; p += 32) s += xb[rr * 1024 + p];
#pragma unroll
            for (int o = 16; o; o >>= 1) s += __shfl_xor_sync(0xffffffffu, s, o);
            if (lane == 0) r[which * 512 + b * 64 + rr] = s;
        }
        return;
    }
    if (blockIdx.x < 208) {
        __shared__ float Xs[16][68], Ys[16][68];
        const int tid = threadIdx.x;
        const int blk = blockIdx.x - 16;
        const int split = blk & 7, pz = blk >> 3;
        const int pair = pz >> 3, b = pz & 7;
        const float* Xb = ((pair == 1) ? x2 : x1) + (long)b * 65536;
        const float* Yb = ((pair == 0) ? x1 : x2) + (long)b * 65536;
        const int kbase = split * 128;
        const int rowt = (tid >> 4) * 4, colt = (tid & 15) * 4;
        const int rr = tid >> 2, cc = (tid & 3) * 4;
        float acc[4][4] = {};

        for (int k0 = kbase; k0 < kbase + 128; k0 += 16) {
            float4 xv = *(const float4*)(Xb + (long)rr * 1024 + k0 + cc);
            float4 yv = *(const float4*)(Yb + (long)rr * 1024 + k0 + cc);
            Xs[cc+0][rr]=xv.x; Xs[cc+1][rr]=xv.y; Xs[cc+2][rr]=xv.z; Xs[cc+3][rr]=xv.w;
            Ys[cc+0][rr]=yv.x; Ys[cc+1][rr]=yv.y; Ys[cc+2][rr]=yv.z; Ys[cc+3][rr]=yv.w;
            __syncthreads();
#pragma unroll
            for (int kk = 0; kk < 16; kk++) {
                float4 a = *(const float4*)&Xs[kk][rowt];
                float4 bq = *(const float4*)&Ys[kk][colt];
                float ra[4]={a.x,a.y,a.z,a.w}, rb[4]={bq.x,bq.y,bq.z,bq.w};
#pragma unroll
                for (int i = 0; i < 4; i++)
#pragma unroll
                    for (int j = 0; j < 4; j++) acc[i][j] += ra[i] * rb[j];
            }
            __syncthreads();
        }
        float* Pp = P + ((long)pz * 8 + split) * 4096;
#pragma unroll
        for (int i = 0; i < 4; i++)
            *(float4*)(Pp + (rowt + i) * 64 + colt) =
                make_float4(acc[i][0], acc[i][1], acc[i][2], acc[i][3]);
        return;
    }

    int gidx = (blockIdx.x - 208) * 256 + threadIdx.x;   // < 524288
    if (gidx < 262144) {
        // bicubic downsample (8-tap AA, edge-renormalized)
        const float* x = gidx < 131072 ? x1 : x2;
        float* y = gidx < 131072 ? y1 : y2;
        int idx = gidx & 131071;
        int ox = idx & 15;
        int oy = (idx >> 4) & 15;
        int bc = idx >> 8;

        int jy0 = 2 * oy - 3, jx0 = 2 * ox - 3;
        float wy[8], wx[8];
        float sy = 0.f, sx = 0.f;
#pragma unroll
        for (int t = 0; t < 8; t++) {
            float w = keys_cubic(fabsf(3.5f - t) * 0.5f);
            int jy = jy0 + t;
            wy[t] = (jy >= 0 && jy < 32) ? w : 0.f; sy += wy[t];
            int jx = jx0 + t;
            wx[t] = (jx >= 0 && jx < 32) ? w : 0.f; sx += wx[t];
        }
        float iy = 1.f / sy, ix = 1.f / sx;
#pragma unroll
        for (int t = 0; t < 8; t++) { wy[t] *= iy; wx[t] *= ix; }

        const float* src = x + (long)bc * 1024;
        float acc = 0.f;
#pragma unroll
        for (int t = 0; t < 8; t++) {
            int jy = min(max(jy0 + t, 0), 31);
            float r2 = 0.f;
#pragma unroll
            for (int u = 0; u < 8; u++) {
                int jx = min(max(jx0 + u, 0), 31);
                r2 += wx[u] * src[jy * 32 + jx];
            }
            acc += wy[t] * r2;
        }
        y[idx] = acc;
    } else {
        // upsample adjoint: Z[b][c][j] = sum_I x[b][c][I] U[I][j]
        int g2 = gidx - 262144;
        const float* x = g2 < 131072 ? x1 : x2;
        float* Z = g2 < 131072 ? Z1 : Z2;
        int idx = g2 & 131071;
        int j = idx & 255;
        int c = (idx >> 8) & 63;
        int b = idx >> 14;
        const float* xr = x + (long)b * 65536 + (long)c * 1024;

        float acc = 0.f;
        int Ilo = max(0, 4 * j - 8), Ihi = min(1023, 4 * j + 10);
        for (int I = Ilo; I <= Ihi; I++) {
            float sf = (I + 0.5f) * 0.25f - 0.5f;
            float fl = floorf(sf);
            float f  = sf - fl;
            int base = (int)fl - 1;
            int tt = j - base;
            if (tt < 0 || tt > 3) continue;
            float tot = 0.f, wsel = 0.f;
#pragma unroll
            for (int t = 0; t < 4; t++) {
                float w = keys_cubic(f + 1.f - t);
                int jj = base + t;
                if (jj < 0 || jj >= 256) w = 0.f;
                tot += w;
                if (t == tt) wsel = w;
            }
            acc += xr[I] * (wsel / tot);
        }
        Z[idx] = acc;
    }
}

// ===========================================================================
// smm / smm128 / cd_stage (in-smem matmuls)
// ===========================================================================
template<int M, int N, int K, bool BT>
__device__ __forceinline__ void smm(const float* __restrict__ A, int lda,
                                    const float* __restrict__ B, int ldb,
                                    float* __restrict__ C, int ldc,
                                    const float* __restrict__ bias,
                                    const float* __restrict__ rscale, int t)
{
    constexpr int RM = M / 16, RN = N / 16;
    const int r0 = (t >> 4) * RM, c0 = (t & 15) * RN;
    float acc[RM][RN];
#pragma unroll
    for (int i = 0; i < RM; i++) {
        float bv = bias ? bias[r0 + i] : 0.f;
#pragma unroll
        for (int j = 0; j < RN; j++) acc[i][j] = bv;
    }
#pragma unroll 4
    for (int k = 0; k < K; k++) {
        float a[RM], b[RN];
#pragma unroll
        for (int i = 0; i < RM; i++) a[i] = A[(r0 + i) * lda + k];
#pragma unroll
        for (int j = 0; j < RN; j++) b[j] = BT ? B[(c0 + j) * ldb + k] : B[k * ldb + c0 + j];
#pragma unroll
        for (int i = 0; i < RM; i++)
#pragma unroll
            for (int j = 0; j < RN; j++) acc[i][j] += a[i] * b[j];
    }
#pragma unroll
    for (int i = 0; i < RM; i++) {
        float sc = rscale ? rscale[r0 + i] : 1.f;
#pragma unroll
        for (int j = 0; j < RN; j++) C[(r0 + i) * ldc + c0 + j] = acc[i][j] * sc;
    }
}

template<int M, int N, int K, bool BT>
__device__ __forceinline__ void smm128(const float* __restrict__ A, int lda,
                                       const float* __restrict__ B, int ldb,
                                       float* __restrict__ C, int ldc,
                                       const float* __restrict__ bias,
                                       const float* __restrict__ rscale, int t)
{
    constexpr int RM = M / 8, RN = N / 16;
    const int r0 = (t >> 4) * RM, c0 = (t & 15) * RN;
    float acc[RM][RN];
#pragma unroll
    for (int i = 0; i < RM; i++) {
        float bv = bias ? bias[r0 + i] : 0.f;
#pragma unroll
        for (int j = 0; j < RN; j++) acc[i][j] = bv;
    }
#pragma unroll 4
    for (int k = 0; k < K; k++) {
        float a[RM], b[RN];
#pragma unroll
        for (int i = 0; i < RM; i++) a[i] = A[(r0 + i) * lda + k];
#pragma unroll
        for (int j = 0; j < RN; j++) b[j] = BT ? B[(c0 + j) * ldb + k] : B[k * ldb + c0 + j];
#pragma unroll
        for (int i = 0; i < RM; i++)
#pragma unroll
            for (int j = 0; j < RN; j++) acc[i][j] += a[i] * b[j];
    }
#pragma unroll
    for (int i = 0; i < RM; i++) {
        float sc = rscale ? rscale[r0 + i] : 1.f;
#pragma unroll
        for (int j = 0; j < RN; j++) C[(r0 + i) * ldc + c0 + j] = acc[i][j] * sc;
    }
}

__device__ __forceinline__ void cd_stage(const float* __restrict__ Mb,
                                         const float* __restrict__ Wd,
                                         float* __restrict__ Cd,
                                         const float* __restrict__ bd,
                                         const float* __restrict__ u, int t)
{
    const int r0 = (t >> 4) * 4, c0 = (t & 15) * 2;
    float acc[4][2] = {};
#pragma unroll 4
    for (int k = 0; k < 64; k++) {
        float a[4], b[2];
#pragma unroll
        for (int i = 0; i < 4; i++) a[i] = Mb[(r0 + i) * 68 + k];
#pragma unroll
        for (int j = 0; j < 2; j++) b[j] = Wd[(c0 + j) * 64 + k];
#pragma unroll
        for (int i = 0; i < 4; i++)
#pragma unroll
            for (int j = 0; j < 2; j++) acc[i][j] += a[i] * b[j];
    }
#pragma unroll
    for (int i = 0; i < 4; i++) {
        int d = r0 + i;
#pragma unroll
        for (int j = 0; j < 2; j++) {
            int e = c0 + j;
            Cd[d * 36 + e] = acc[i][j] + bd[d]*u[e] + bd[e]*u[d] + 1024.f*bd[d]*bd[e];
        }
    }
}

// ===========================================================================
// chan_fused: 16 blocks (batch x dir); X1C/X2C reduced inline from PART.
// ===========================================================================
__global__ void __launch_bounds__(256)
chan_fused_k(const float* __restrict__ PART, const float* __restrict__ rsum,
             const float* __restrict__ w_down, const float* __restrict__ b_down,
             const float* __restrict__ w_up, const float* __restrict__ b_up,
             float* __restrict__ CH1_g, float* __restrict__ CH2_g)
{
    extern __shared__ float sm[];
    float* A   = sm;              // 64x68  X1C -> U
    float* Bf  = A   + 4352;      // 64x68  X2C
    float* LC  = Bf  + 4352;
    float* E   = LC  + 4352;
    float* Wd  = E   + 4352;      // 32x64
    float* Wu  = Wd  + 2048;      // 64x32
    float* Mb1 = Wu  + 2048;      // 32x68
    float* Mb2 = Mb1 + 2176;
    float* C1d = Mb2 + 2176;      // 32x36
    float* C2d = C1d + 1152;
    float* LCD = C2d + 1152;
    float* Ad  = LCD + 1152;
    float* TT  = Ad  + 1152;      // 64x36
    float* bd  = TT  + 2304;
    float* bu  = bd  + 32;
    float* u1  = bu  + 64;
    float* u2  = u1  + 32;
    float* st  = u2  + 32;        // 128

    const int bi = blockIdx.x >> 1, dir = blockIdx.x & 1;
    const int t = threadIdx.x;
    const bool h0 = t < 128;
    const int ht = h0 ? t : t - 128;

    for (int i = t; i < 4096; i += 256) {
        float s1 = 0.f, s2 = 0.f;
#pragma unroll
        for (int s = 0; s < 8; s++) {
            s1 += PART[((long)bi * 8 + s) * 4096 + i];          // pair0: pz=bi
            s2 += PART[((long)(8 + bi) * 8 + s) * 4096 + i];    // pair1
        }
        A [(i >> 6) * 68 + (i & 63)] = s1;
        Bf[(i >> 6) * 68 + (i & 63)] = s2;
    }
    for (int i = t; i < 2048; i += 256) { Wd[i] = w_down[i]; Wu[i] = w_up[i]; }
    if (t < 32) bd[t] = b_down[t];
    if (t < 64) bu[t] = b_up[t];
    __syncthreads();

    if (t < 64) {
        int d = t & 31, which = t >> 5;
        const float* r = rsum + which * 512 + bi * 64;
        float s = 0.f;
        for (int c = 0; c < 64; c++) s += Wd[d * 64 + c] * r[c];
        (which ? u2 : u1)[d] = s;
    }
    __syncthreads();

    if (h0) smm128<32, 64, 64, false>(Wd, 64, A, 68, Mb1, 68, nullptr, nullptr, ht);
    else    smm128<32, 64, 64, false>(Wd, 64, Bf, 68, Mb2, 68, nullptr, nullptr, ht);
    __syncthreads();
    if (h0) cd_stage(Mb1, Wd, C1d, bd, u1, ht);
    else    cd_stage(Mb2, Wd, C2d, bd, u2, ht);
    __syncthreads();

    smm<64, 64, 64, false>(A, 68, Bf, 68, LC, 68, nullptr, nullptr, t);
    __syncthreads();

    if (t < 64) {
        float m = -3.4e38f;
        if (dir == 0) {
            for (int j = 0; j < 64; j++) m = fmaxf(m, LC[t * 68 + j]);
            float s = 0.f;
            for (int j = 0; j < 64; j++) s += __expf(LC[t * 68 + j] - m);
            st[t] = m; st[64 + t] = 1.f / s;
        } else {
            for (int j = 0; j < 64; j++) m = fmaxf(m, LC[j * 68 + t]);
            float s = 0.f;
            for (int j = 0; j < 64; j++) s += __expf(LC[j * 68 + t] - m);
            st[t] = m; st[64 + t] = 1.f / s;
        }
    } else if (t >= 128) {
        smm128<32, 32, 32, false>(C1d, 36, C2d, 36, LCD, 36, nullptr, nullptr, ht);
    }
    __syncthreads();

    if (t < 32) {
        float m = -3.4e38f;
        if (dir == 0) {
            for (int j = 0; j < 32; j++) m = fmaxf(m, LCD[t * 36 + j]);
            float s = 0.f;
            for (int j = 0; j < 32; j++) s += __expf(LCD[t * 36 + j] - m);
            float inv = 1.f / s;
            for (int j = 0; j < 32; j++) Ad[t * 36 + j] = __expf(LCD[t * 36 + j] - m) * inv;
        } else {
            for (int j = 0; j < 32; j++) m = fmaxf(m, LCD[j * 36 + t]);
            float s = 0.f;
            for (int j = 0; j < 32; j++) s += __expf(LCD[j * 36 + t] - m);
            float inv = 1.f / s;
            for (int j = 0; j < 32; j++) Ad[t * 36 + j] = __expf(LCD[j * 36 + t] - m) * inv;
        }
    } else if (t >= 64) {
        for (int o = t - 64; o < 4096; o += 192) {
            int i = o >> 6, j = o & 63;
            E[i * 68 + j] = dir == 0 ? __expf(LC[i * 68 + j] - st[i])
                                     : __expf(LC[j * 68 + i] - st[i]);
        }
    }
    __syncthreads();

    smm<64, 32, 32, false>(Wu, 32, Ad, 36, TT, 36, bu, nullptr, t);
    __syncthreads();
    smm<64, 64, 32, true >(Wu, 32, TT, 36, A, 68, bu, nullptr, t);
    __syncthreads();

    float* CHo = (dir == 0 ? CH1_g : CH2_g) + bi * 4096;
    smm<64, 64, 64, true>(E, 68, A, 68, CHo, 64, nullptr, st + 64, t);
}

// ===========================================================================
// trio_k: three M=64,N=1024,K=64 NN GEMMs; G12 reduced inline from PART;
// CH stats accumulated into MV via atomics. grid (16, 24).
// ===========================================================================
__global__ void __launch_bounds__(256)
trio_k(const float* __restrict__ CH1, const float* __restrict__ CH2,
       const float* __restrict__ PART,
       const float* __restrict__ x1, const float* __restrict__ x2,
       float* __restrict__ CH1O, float* __restrict__ CH2O, float* __restrict__ PP,
       float* __restrict__ MV)
{
    __shared__ float Af[64 * 72];
    __shared__ float As[16][68];
    __shared__ float Bs[16][68];
    __shared__ float s_sum[64], s_sq[64];
    const int tid = threadIdx.x;
    const int z = blockIdx.y, pair = z >> 3, b = z & 7;
    const int n0 = blockIdx.x * 64;
    const float* Bb = (pair == 0 ? x1 : x2) + (long)b * 65536;
    float* Cb = (pair == 0 ? CH1O : pair == 1 ? CH2O : PP) + (long)b * 65536;
    const int rowt = (tid >> 4) * 4, colt = (tid & 15) * 4;
    float acc[4][4] = {};

    // stage full A matrix (CH from global; G12 = sum of PART splits)
    for (int i = tid; i < 4096; i += 256) {
        float v;
        if (pair == 2) {
            v = 0.f;
#pragma unroll
            for (int s = 0; s < 8; s++) v += PART[((long)(16 + b) * 8 + s) * 4096 + i];
        } else {
            v = (pair == 0 ? CH1 : CH2)[(long)b * 4096 + i];
        }
        Af[(i >> 6) * 72 + (i & 63)] = v;
    }
    if (tid < 64) { s_sum[tid] = 0.f; s_sq[tid] = 0.f; }
    __syncthreads();

    for (int k0 = 0; k0 < 64; k0 += 16) {
        {
            int r = tid >> 2, c = (tid & 3) * 4;
            float4 av = *(const float4*)&Af[r * 72 + k0 + c];
            As[c+0][r]=av.x; As[c+1][r]=av.y; As[c+2][r]=av.z; As[c+3][r]=av.w;
        }
        {
            int kr = tid >> 4, nc = (tid & 15) * 4;
            float4 bv = *(const float4*)(Bb + (long)(k0 + kr) * 1024 + n0 + nc);
            *(float4*)&Bs[kr][nc] = bv;
        }
        __syncthreads();
#pragma unroll
        for (int kk = 0; kk < 16; kk++) {
            float4 a = *(const float4*)&As[kk][rowt];
            float4 bq = *(const float4*)&Bs[kk][colt];
            float ra[4] = {a.x,a.y,a.z,a.w}, rb[4] = {bq.x,bq.y,bq.z,bq.w};
#pragma unroll
            for (int i = 0; i < 4; i++)
#pragma unroll
                for (int j = 0; j < 4; j++) acc[i][j] += ra[i] * rb[j];
        }
        __syncthreads();
    }
#pragma unroll
    for (int i = 0; i < 4; i++)
        *(float4*)(Cb + (long)(rowt + i) * 1024 + n0 + colt) =
            make_float4(acc[i][0], acc[i][1], acc[i][2], acc[i][3]);

    // CH BN partial sums (pairs 0,1): per-channel (row) sums over this tile
    if (pair < 2) {
#pragma unroll
        for (int i = 0; i < 4; i++) {
            float s = acc[i][0] + acc[i][1] + acc[i][2] + acc[i][3];
            float q = acc[i][0]*acc[i][0] + acc[i][1]*acc[i][1]
                    + acc[i][2]*acc[i][2] + acc[i][3]*acc[i][3];
            atomicAdd(&s_sum[rowt + i], s);
            atomicAdd(&s_sq[rowt + i], q);
        }
        __syncthreads();
        if (tid < 64) {
            atomicAdd(&MV[pair * 128 + tid], s_sum[tid]);
            atomicAdd(&MV[pair * 128 + 64 + tid], s_sq[tid]);
        }
    }
}

// ===========================================================================
// lbgemm: LB = x1^T @ PP + row/col maxes via encoded atomics. grid (16,16,8).
// ===========================================================================
__global__ void __launch_bounds__(256)
lbgemm_k(const float* __restrict__ X1, const float* __restrict__ PP,
         float* __restrict__ LB, unsigned* __restrict__ RSME, unsigned* __restrict__ CSME)
{
    __shared__ float As[16][68];
    __shared__ float Bs[16][68];
    __shared__ unsigned srow[64], scol[64];
    const int tid = threadIdx.x;
    const int m0 = blockIdx.y * 64, n0 = blockIdx.x * 64, b = blockIdx.z;
    const float* Ab = X1 + (long)b * 65536;
    const float* Bb = PP + (long)b * 65536;
    float* Cb = LB + (long)b * 1048576;
    const int rowt = (tid >> 4) * 4, colt = (tid & 15) * 4;
    const int kr = tid >> 4, xc = (tid & 15) * 4;
    float acc[4][4] = {};

    if (tid < 64) { srow[tid] = 0u; scol[tid] = 0u; }

    for (int k0 = 0; k0 < 64; k0 += 16) {
        *(float4*)&As[kr][xc] = *(const float4*)(Ab + (long)(k0 + kr) * 1024 + m0 + xc);
        *(float4*)&Bs[kr][xc] = *(const float4*)(Bb + (long)(k0 + kr) * 1024 + n0 + xc);
        __syncthreads();
#pragma unroll
        for (int kk = 0; kk < 16; kk++) {
            float4 a = *(const float4*)&As[kk][rowt];
            float4 bq = *(const float4*)&Bs[kk][colt];
            float ra[4] = {a.x,a.y,a.z,a.w}, rb[4] = {bq.x,bq.y,bq.z,bq.w};
#pragma unroll
            for (int i = 0; i < 4; i++)
#pragma unroll
                for (int j = 0; j < 4; j++) acc[i][j] += ra[i] * rb[j];
        }
        __syncthreads();
    }

#pragma unroll
    for (int i = 0; i < 4; i++)
        *(float4*)(Cb + (long)(m0 + rowt + i) * 1024 + n0 + colt) =
            make_float4(acc[i][0], acc[i][1], acc[i][2], acc[i][3]);

#pragma unroll
    for (int i = 0; i < 4; i++) {
        float rm = fmaxf(fmaxf(acc[i][0], acc[i][1]), fmaxf(acc[i][2], acc[i][3]));
        atomicMax(&srow[rowt + i], fenc(rm));
    }
#pragma unroll
    for (int j = 0; j < 4; j++) {
        float cm = fmaxf(fmaxf(acc[0][j], acc[1][j]), fmaxf(acc[2][j], acc[3][j]));
        atomicMax(&scol[colt + j], fenc(cm));
    }
    __syncthreads();
    if (tid < 64)       atomicMax(&RSME[b * 1024 + m0 + tid], srow[tid]);
    else if (tid < 128) atomicMax(&CSME[b * 1024 + n0 + (tid - 64)], scol[tid - 64]);
}

// ===========================================================================
// fdchain_k: GD = XDN1 XDN2^T ; PD = GD XDN2 ; LFD = XDN1^T PD.
// grid (4, 8): (col slice, batch). GD/PD computed redundantly per slice.
// ===========================================================================
__global__ void __launch_bounds__(256)
fdchain_k(const float* __restrict__ XDN1, const float* __restrict__ XDN2,
          float* __restrict__ LFD)
{
    extern __shared__ float fsm[];
    float* Xs  = fsm;             // 16x68
    float* Ys  = Xs  + 1088;      // 16x68
    float* GDs = Ys  + 1088;      // 64x68
    float* X2s = GDs + 4352;      // 64x68 (slice)
    float* PDs = X2s + 4352;      // 64x68 (slice)
    float* X1s = PDs + 4352;      // 64x260

    const int tid = threadIdx.x;
    const int s0 = blockIdx.x * 64, b = blockIdx.y;
    const float* X1g = XDN1 + (long)b * 16384;
    const float* X2g = XDN2 + (long)b * 16384;
    const int rowt = (tid >> 4) * 4, colt = (tid & 15) * 4;

    // --- GD gram (K=256) ---
    {
        float acc[4][4] = {};
        const int rr = tid >> 2, cc = (tid & 3) * 4;
        for (int k0 = 0; k0 < 256; k0 += 16) {
            float4 xv = *(const float4*)(X1g + (long)rr * 256 + k0 + cc);
            float4 yv = *(const float4*)(X2g + (long)rr * 256 + k0 + cc);
            Xs[(cc+0)*68+rr]=xv.x; Xs[(cc+1)*68+rr]=xv.y; Xs[(cc+2)*68+rr]=xv.z; Xs[(cc+3)*68+rr]=xv.w;
            Ys[(cc+0)*68+rr]=yv.x; Ys[(cc+1)*68+rr]=yv.y; Ys[(cc+2)*68+rr]=yv.z; Ys[(cc+3)*68+rr]=yv.w;
            __syncthreads();
#pragma unroll
            for (int kk = 0; kk < 16; kk++) {
                float4 a = *(const float4*)&Xs[kk*68 + rowt];
                float4 bq = *(const float4*)&Ys[kk*68 + colt];
                float ra[4]={a.x,a.y,a.z,a.w}, rb[4]={bq.x,bq.y,bq.z,bq.w};
#pragma unroll
                for (int i = 0; i < 4; i++)
#pragma unroll
                    for (int j = 0; j < 4; j++) acc[i][j] += ra[i] * rb[j];
            }
            __syncthreads();
        }
#pragma unroll
        for (int i = 0; i < 4; i++)
#pragma unroll
            for (int j = 0; j < 4; j++) GDs[(rowt + i) * 68 + colt + j] = acc[i][j];
    }
    // --- stage XDN2 slice + XDN1 full ---
    for (int i = tid; i < 4096; i += 256)
        X2s[(i >> 6) * 68 + (i & 63)] = X2g[(long)(i >> 6) * 256 + s0 + (i & 63)];
    for (int i = tid; i < 16384; i += 256)
        X1s[(i >> 8) * 260 + (i & 255)] = X1g[i];
    __syncthreads();

    // --- PD slice: PDs[c][q] = sum_e GDs[c][e] X2s[e][q] ---
    {
        float acc[4][4] = {};
#pragma unroll 4
        for (int e = 0; e < 64; e++) {
            float a[4], bq[4];
#pragma unroll
            for (int i = 0; i < 4; i++) a[i] = GDs[(rowt + i) * 68 + e];
#pragma unroll
            for (int j = 0; j < 4; j++) bq[j] = X2s[e * 68 + colt + j];
#pragma unroll
            for (int i = 0; i < 4; i++)
#pragma unroll
                for (int j = 0; j < 4; j++) acc[i][j] += a[i] * bq[j];
        }
        __syncthreads();
#pragma unroll
        for (int i = 0; i < 4; i++)
#pragma unroll
            for (int j = 0; j < 4; j++) PDs[(rowt + i) * 68 + colt + j] = acc[i][j];
    }
    __syncthreads();

    // --- LFD slice: LFD[p][s0+q] = sum_c X1s[c][p] PDs[c][q] ---
    {
        const int pr0 = (tid >> 4) * 16, q0 = (tid & 15) * 4;
        float acc[16][4] = {};
#pragma unroll 2
        for (int c = 0; c < 64; c++) {
            float a[16], bq[4];
#pragma unroll
            for (int i = 0; i < 16; i++) a[i] = X1s[c * 260 + pr0 + i];
#pragma unroll
            for (int j = 0; j < 4; j++) bq[j] = PDs[c * 68 + q0 + j];
#pragma unroll
            for (int i = 0; i < 16; i++)
#pragma unroll
                for (int j = 0; j < 4; j++) acc[i][j] += a[i] * bq[j];
        }
        float* Lg = LFD + (long)b * 65536;
#pragma unroll
        for (int i = 0; i < 16; i++)
            *(float4*)(Lg + (long)(pr0 + i) * 256 + s0 + q0) =
                make_float4(acc[i][0], acc[i][1], acc[i][2], acc[i][3]);
    }
}

// ===========================================================================
// softLFD: blocks 0..2047 row softmax; 2048..2079 col-T softmax. N=256.
// ===========================================================================
__global__ void softLFD_k(const float* __restrict__ L,
                          float* __restrict__ AFD12, float* __restrict__ AFD21T)
{
    if (blockIdx.x < 2048) {
        long row = blockIdx.x;
        const float* p = L + row * 256;
        float* q = AFD12 + row * 256;
        int t = threadIdx.x;
        __shared__ float sh[8];

        float m = -3.4e38f;
        for (int i = t; i < 256; i += 256) m = fmaxf(m, p[i]);
#pragma unroll
        for (int o = 16; o; o >>= 1) m = fmaxf(m, __shfl_xor_sync(0xffffffffu, m, o));
        if ((t & 31) == 0) sh[t >> 5] = m;
        __syncthreads();
        float mm = sh[0];
#pragma unroll
        for (int w = 1; w < 8; w++) mm = fmaxf(mm, sh[w]);
        __syncthreads();

        float s = __expf(p[t] - mm);
        float sv = s;
#pragma unroll
        for (int o = 16; o; o >>= 1) s += __shfl_xor_sync(0xffffffffu, s, o);
        if ((t & 31) == 0) sh[t >> 5] = s;
        __syncthreads();
        float ss = 0.f;
#pragma unroll
        for (int w = 0; w < 8; w++) ss += sh[w];
        q[t] = sv / ss;
    } else {
        int blk = blockIdx.x - 2048;
        int cc = threadIdx.x & 63;
        int kg = threadIdx.x >> 6;
        int bi = blk >> 2;
        int i  = (blk & 3) * 64 + cc;
        const float* Lb = L      + (long)bi * 65536;
        float*       Ab = AFD21T + (long)bi * 65536;
        __shared__ float red[4][64];

        float m = -3.4e38f;
        for (int k = kg; k < 256; k += 4) m = fmaxf(m, Lb[k * 256 + i]);
        red[kg][cc] = m;
        __syncthreads();
        m = fmaxf(fmaxf(red[0][cc], red[1][cc]), fmaxf(red[2][cc], red[3][cc]));
        __syncthreads();

        float s = 0.f;
        for (int k = kg; k < 256; k += 4) s += __expf(Lb[k * 256 + i] - m);
        red[kg][cc] = s;
        __syncthreads();
        s = red[0][cc] + red[1][cc] + red[2][cc] + red[3][cc];
        float inv = 1.f / s;

        for (int k = kg; k < 256; k += 4)
            Ab[k * 256 + i] = __expf(Lb[k * 256 + i] - m) * inv;
    }
}

// ===========================================================================
// ypair: Y1 = AFD12 @ Z1^T ; Y2 = AFD21T^T @ Z2^T. grid (4, 8, 2).
// ===========================================================================
__global__ void __launch_bounds__(256)
ypair_k(const float* __restrict__ AFD12, const float* __restrict__ AFD21T,
        const float* __restrict__ Z1, const float* __restrict__ Z2,
        float* __restrict__ Y1, float* __restrict__ Y2)
{
    __shared__ float As[16][68];
    __shared__ float Bs[16][68];
    const int tid = threadIdx.x;
    const int m0 = blockIdx.x * 64, b = blockIdx.y, dir = blockIdx.z;
    const float* Ab = (dir ? AFD21T : AFD12) + (long)b * 65536;
    const float* Zb = (dir ? Z2 : Z1) + (long)b * 16384;
    float* Yb = (dir ? Y2 : Y1) + (long)b * 16384;
    const int rowt = (tid >> 4) * 4, colt = (tid & 15) * 4;
    float acc[4][4] = {};

    for (int k0 = 0; k0 < 256; k0 += 16) {
        if (dir == 0) {
            int r = tid >> 2, c = (tid & 3) * 4;
            float4 av = *(const float4*)(Ab + (long)(m0 + r) * 256 + k0 + c);
            As[c+0][r]=av.x; As[c+1][r]=av.y; As[c+2][r]=av.z; As[c+3][r]=av.w;
        } else {
            int kr = tid >> 4, mc = (tid & 15) * 4;
            *(float4*)&As[kr][mc] = *(const float4*)(Ab + (long)(k0 + kr) * 256 + m0 + mc);
        }
        {
            int r = tid >> 2, c = (tid & 3) * 4;
            float4 bv = *(const float4*)(Zb + (long)r * 256 + k0 + c);
            Bs[c+0][r]=bv.x; Bs[c+1][r]=bv.y; Bs[c+2][r]=bv.z; Bs[c+3][r]=bv.w;
        }
        __syncthreads();
#pragma unroll
        for (int kk = 0; kk < 16; kk++) {
            float4 a = *(const float4*)&As[kk][rowt];
            float4 bq = *(const float4*)&Bs[kk][colt];
            float ra[4]={a.x,a.y,a.z,a.w}, rb[4]={bq.x,bq.y,bq.z,bq.w};
#pragma unroll
            for (int i = 0; i < 4; i++)
#pragma unroll
                for (int j = 0; j < 4; j++) acc[i][j] += ra[i] * rb[j];
        }
        __syncthreads();
    }
#pragma unroll
    for (int i = 0; i < 4; i++)
        *(float4*)(Yb + (long)(m0 + rowt + i) * 64 + colt) =
            make_float4(acc[i][0], acc[i][1], acc[i][2], acc[i][3]);
}

// W[b][I][c] = sum_t w_t(I) Y[b][base+t][c]
__global__ void upapply2_k(const float* __restrict__ Y1, const float* __restrict__ Y2,
                           float* __restrict__ W1, float* __restrict__ W2)
{
    int gidx = blockIdx.x * 256 + threadIdx.x;
    if (gidx >= 1048576) return;
    const float* Y = gidx < 524288 ? Y1 : Y2;
    float* Wo = gidx < 524288 ? W1 : W2;
    int idx = gidx & 524287;
    int c = idx & 63;
    int I = (idx >> 6) & 1023;
    int b = idx >> 16;

    float sf = (I + 0.5f) * 0.25f - 0.5f;
    float fl = floorf(sf);
    float f  = sf - fl;
    int base = (int)fl - 1;
    float w[4], tot = 0.f;
#pragma unroll
    for (int t = 0; t < 4; t++) {
        float ww = keys_cubic(f + 1.f - t);
        int jj = base + t;
        if (jj < 0 || jj >= 256) ww = 0.f;
        w[t] = ww; tot += ww;
    }
    float inv = 1.f / tot;
    const float* Yb = Y + (long)b * 16384;
    float acc = 0.f;
#pragma unroll
    for (int t = 0; t < 4; t++)
        if (w[t] != 0.f) acc += w[t] * Yb[(base + t) * 64 + c];
    Wo[idx] = acc * inv;
}

// ===========================================================================
// av_k: merged row/col fused softmax·W (grid (16,8,2), z=dir) with
// threshold exp, tile skip, inline sums, and HW BN partial sums.
// ===========================================================================
__global__ void __launch_bounds__(256)
av_k(const float* __restrict__ L, const float* __restrict__ W1,
     const float* __restrict__ W2,
     const unsigned* __restrict__ RSME, const unsigned* __restrict__ CSME,
     float* __restrict__ O1, float* __restrict__ O2, float* __restrict__ MV)
{
    __shared__ float Ls[16][68], Ws[16][68];
    __shared__ float smx[64], spart[256], sinv[64];
    __shared__ float scs[16][64];
    __shared__ float s_sum[64], s_sq[64];
    const int tid = threadIdx.x;
    const int b = blockIdx.y, m0 = blockIdx.x * 64, dir = blockIdx.z;
    const unsigned* ME = dir ? CSME : RSME;
    if (tid < 64) { smx[tid] = fdec(ME[b * 1024 + m0 + tid]); s_sum[tid] = 0.f; s_sq[tid] = 0.f; }
    __syncthreads();
    const float* Lb = L + (long)b * 1048576;
    const float* Wb = (dir ? W2 : W1) + (long)b * 65536;
    const int rowt = (tid >> 4) * 4, colt = (tid & 15) * 4;
    float acc[4][4] = {};

    if (dir == 0) {
        const int r = tid >> 2, c = (tid & 3) * 4;
        const int kr = tid >> 4, nc = (tid & 15) * 4;
        float psum = 0.f;
        const float mr = smx[r], thr = mr - 20.f;
        for (int k0 = 0; k0 < 1024; k0 += 16) {
            float4 v = *(const float4*)(Lb + (long)(m0 + r) * 1024 + k0 + c);
            float4 e = {0.f, 0.f, 0.f, 0.f};
            int live = 0;
            if (v.x > thr || v.y > thr || v.z > thr || v.w > thr) {
                e.x = __expf(v.x - mr); e.y = __expf(v.y - mr);
                e.z = __expf(v.z - mr); e.w = __expf(v.w - mr);
                psum += e.x + e.y + e.z + e.w;
                live = 1;
            }
            Ls[c+0][r] = e.x; Ls[c+1][r] = e.y; Ls[c+2][r] = e.z; Ls[c+3][r] = e.w;
            *(float4*)&Ws[kr][nc] = *(const float4*)(Wb + (long)(k0 + kr) * 64 + nc);
            int any = __syncthreads_or(live);
            if (any) {
#pragma unroll
                for (int kk = 0; kk < 16; kk++) {
                    float4 a = *(const float4*)&Ls[kk][rowt];
                    float4 w = *(const float4*)&Ws[kk][colt];
                    float ra[4]={a.x,a.y,a.z,a.w}, rb[4]={w.x,w.y,w.z,w.w};
#pragma unroll
                    for (int i = 0; i < 4; i++)
#pragma unroll
                        for (int j = 0; j < 4; j++) acc[i][j] += ra[i] * rb[j];
                }
            }
            __syncthreads();
        }
        spart[tid] = psum;
        __syncthreads();
        if (tid < 64)
            sinv[tid] = 1.f / (spart[4*tid] + spart[4*tid+1] + spart[4*tid+2] + spart[4*tid+3]);
        __syncthreads();
    } else {
        const int kr = tid >> 4, mc = (tid & 15) * 4;
        float ps[4] = {0.f, 0.f, 0.f, 0.f};
        const float m0f = smx[mc], m1f = smx[mc+1], m2f = smx[mc+2], m3f = smx[mc+3];
        for (int k0 = 0; k0 < 1024; k0 += 16) {
            float4 v = *(const float4*)(Lb + (long)(k0 + kr) * 1024 + m0 + mc);
            float4 e = {0.f, 0.f, 0.f, 0.f};
            int live = 0;
            if (v.x > m0f - 20.f || v.y > m1f - 20.f || v.z > m2f - 20.f || v.w > m3f - 20.f) {
                e.x = (v.x > m0f - 20.f) ? __expf(v.x - m0f) : 0.f;
                e.y = (v.y > m1f - 20.f) ? __expf(v.y - m1f) : 0.f;
                e.z = (v.z > m2f - 20.f) ? __expf(v.z - m2f) : 0.f;
                e.w = (v.w > m3f - 20.f) ? __expf(v.w - m3f) : 0.f;
                ps[0] += e.x; ps[1] += e.y; ps[2] += e.z; ps[3] += e.w;
                live = 1;
            }
            *(float4*)&Ls[kr][mc] = e;
            *(float4*)&Ws[kr][mc] = *(const float4*)(Wb + (long)(k0 + kr) * 64 + mc);
            int any = __syncthreads_or(live);
            if (any) {
#pragma unroll
                for (int kk = 0; kk < 16; kk++) {
                    float4 a = *(const float4*)&Ls[kk][rowt];
                    float4 w = *(const float4*)&Ws[kk][colt];
                    float ra[4]={a.x,a.y,a.z,a.w}, rb[4]={w.x,w.y,w.z,w.w};
#pragma unroll
                    for (int i = 0; i < 4; i++)
#pragma unroll
                        for (int j = 0; j < 4; j++) acc[i][j] += ra[i] * rb[j];
                }
            }
            __syncthreads();
        }
#pragma unroll
        for (int j = 0; j < 4; j++) scs[kr][mc + j] = ps[j];
        __syncthreads();
        if (tid < 64) {
            float s = 0.f;
#pragma unroll
            for (int k = 0; k < 16; k++) s += scs[k][tid];
            sinv[tid] = 1.f / s;
        }
        __syncthreads();
    }

    float* Ob = (dir ? O2 : O1) + (long)b * 65536;
    float psumC[4] = {0,0,0,0}, psqC[4] = {0,0,0,0};
#pragma unroll
    for (int i = 0; i < 4; i++) {
        float sc = sinv[rowt + i];
        float v0 = acc[i][0]*sc, v1 = acc[i][1]*sc, v2 = acc[i][2]*sc, v3 = acc[i][3]*sc;
        *(float4*)(Ob + (long)(m0 + rowt + i) * 64 + colt) = make_float4(v0, v1, v2, v3);
        psumC[0] += v0; psumC[1] += v1; psumC[2] += v2; psumC[3] += v3;
        psqC[0] += v0*v0; psqC[1] += v1*v1; psqC[2] += v2*v2; psqC[3] += v3*v3;
    }
#pragma unroll
    for (int j = 0; j < 4; j++) {
        atomicAdd(&s_sum[colt + j], psumC[j]);
        atomicAdd(&s_sq[colt + j], psqC[j]);
    }
    __syncthreads();
    if (tid < 64) {
        atomicAdd(&MV[(2 + dir) * 128 + tid], s_sum[tid]);
        atomicAdd(&MV[(2 + dir) * 128 + 64 + tid], s_sq[tid]);
    }
}

// ---------------------------------------------------------------------------
// Finalize: mean/var computed inline from accumulated sums.
// ---------------------------------------------------------------------------
__global__ void finalize_k(const float* __restrict__ x1, const float* __restrict__ x2,
                           const float* __restrict__ ch1o, const float* __restrict__ ch2o,
                           const float* __restrict__ hw1t, const float* __restrict__ hw2t,
                           const float* __restrict__ mv,
                           const float* __restrict__ gamma, const float* __restrict__ beta,
                           float* __restrict__ out)
{
    int idx = blockIdx.x * 256 + threadIdx.x;
    if (idx >= 524288) return;
    int c = (idx >> 10) & 63;
    long hwi = ((long)(idx >> 16)) * 65536 + (long)(idx & 1023) * 64 + c;
    float g = gamma[c], be = beta[c];
    const float inv8192 = 1.f / 8192.f;

    float mean0 = mv[c] * inv8192;
    float var0  = fmaxf(mv[64 + c] * inv8192 - mean0 * mean0, 0.f);
    float mean1 = mv[128 + c] * inv8192;
    float var1  = fmaxf(mv[192 + c] * inv8192 - mean1 * mean1, 0.f);
    float mean2 = mv[256 + c] * inv8192;
    float var2  = fmaxf(mv[320 + c] * inv8192 - mean2 * mean2, 0.f);
    float mean3 = mv[384 + c] * inv8192;
    float var3  = fmaxf(mv[448 + c] * inv8192 - mean3 * mean3, 0.f);

    float xa = x1[idx], xb = x2[idx];

    float v, r;
    v = (ch1o[idx] - mean0) * rsqrtf(var0 + 1e-5f) * g + be + xa;
    r = fmaxf(v, 0.f);
    v = (hw1t[hwi] - mean2) * rsqrtf(var2 + 1e-5f) * g + be + xa;
    out[idx] = 0.5f * (r + fmaxf(v, 0.f));

    v = (ch2o[idx] - mean1) * rsqrtf(var1 + 1e-5f) * g + be + xb;
    r = fmaxf(v, 0.f);
    v = (hw2t[hwi] - mean3) * rsqrtf(var3 + 1e-5f) * g + be + xb;
    out[524288 + idx] = 0.5f * (r + fmaxf(v, 0.f));
}

// ===========================================================================
extern "C" void kernel_launch(void* const* d_in, const int* in_sizes, int n_in,
                              void* d_out, int out_size)
{
    const float* x1     = (const float*)d_in[0];
    const float* x2     = (const float*)d_in[1];
    const float* w_down = (const float*)d_in[2];
    const float* b_down = (const float*)d_in[3];
    const float* w_up   = (const float*)d_in[4];
    const float* b_up   = (const float*)d_in[5];
    const float* gamma  = (const float*)d_in[6];
    const float* beta   = (const float*)d_in[7];
    float* out = (float*)d_out;

    float* base = nullptr;
    cudaGetSymbolAddress((void**)&base, g_buf);

    float* LB = base;                      // [8,1024,1024]
    float* S  = base + 8ll * 1024 * 1024;
    float* CH1   = S; S += 32768;
    float* CH2   = S; S += 32768;
    float* CH1O  = S; S += 524288;
    float* CH2O  = S; S += 524288;
    float* XDN1  = S; S += 131072;
    float* XDN2  = S; S += 131072;
    float* LFD   = S; S += 524288;
    float* AFD12 = S; S += 524288;
    float* AFD21T= S; S += 524288;
    float* Z1    = S; S += 131072;
    float* Z2    = S; S += 131072;
    float* Y1    = S; S += 131072;
    float* Y2    = S; S += 131072;
    float* W1    = S; S += 524288;
    float* W2    = S; S += 524288;
    float* HW1OT = S; S += 524288;
    float* HW2OT = S; S += 524288;
    float* PP    = S; S += 524288;
    unsigned* RSME = (unsigned*)S; S += 8192;
    unsigned* CSME = (unsigned*)S; S += 8192;
    float* R12   = S; S += 1024;
    float* PART  = S; S += 786432;
    float* MV    = S; S += 512;

    const int CHAN_SMEM = 33056 * 4;
    const int FD_SMEM   = 31872 * 4;
    cudaFuncSetAttribute(chan_fused_k, cudaFuncAttributeMaxDynamicSharedMemorySize, CHAN_SMEM);
    cudaFuncSetAttribute(fdchain_k,    cudaFuncAttributeMaxDynamicSharedMemorySize, FD_SMEM);

    // 1: rowsums + zero ME/MV + gram splits + resample
    prep_k<<<2256, 256>>>(x1, x2, R12, RSME, MV, PART, XDN1, XDN2, Z1, Z2);
    // 2: fused channel path (inline gram reduction)
    chan_fused_k<<<16, 256, CHAN_SMEM>>>(PART, R12, w_down, b_down, w_up, b_up, CH1, CH2);
    // 3: CH1O/CH2O/PP GEMMs (+ CH BN sums)
    trio_k<<<dim3(16, 24), 256>>>(CH1, CH2, PART, x1, x2, CH1O, CH2O, PP, MV);
    // 4: big logits + row/col maxes
    lbgemm_k<<<dim3(16, 16, 8), 256>>>(x1, PP, LB, RSME, CSME);
    // 5: GD + PD + LFD fused
    fdchain_k<<<dim3(4, 8), 256, FD_SMEM>>>(XDN1, XDN2, LFD);
    // 6: LFD softmaxes (row + transposed col)
    softLFD_k<<<2080, 256>>>(LFD, AFD12, AFD21T);
    // 7: Y GEMM pair
    ypair_k<<<dim3(4, 8, 2), 256>>>(AFD12, AFD21T, Z1, Z2, Y1, Y2);
    // 8: apply upsample operator
    upapply2_k<<<4096, 256>>>(Y1, Y2, W1, W2);
    // 9: fused softmax(L)@W, both directions (+ HW BN sums)
    av_k<<<dim3(16, 8, 2), 256>>>(LB, W1, W2, RSME, CSME, HW1OT, HW2OT, MV);
    // 10: BN (inline) + residual + relu + average
    finalize_k<<<2048, 256>>>(x1, x2, CH1O, CH2O, HW1OT, HW2OT, MV, gamma, beta, out);
}